// round 1
// baseline (speedup 1.0000x reference)
#include <cuda_runtime.h>
#include <cuda_bf16.h>

// WaveletTransformer: 4-level Haar DWT immediately inverted by its exact IDWT.
// Orthogonal perfect-reconstruction => output == input to ~2.4e-7 rel err
// (fp32 (2*INV_SQRT2^2)^4 drift), far inside the 1e-3 threshold.
// So the optimal kernel is a pure bandwidth-bound copy.

__global__ void __launch_bounds__(512, 2)
copy_identity_kernel(const float4* __restrict__ in, float4* __restrict__ out, long long n4) {
    long long i = (long long)blockIdx.x * blockDim.x + threadIdx.x;
    long long stride = (long long)gridDim.x * blockDim.x;
    for (; i < n4; i += stride) {
        out[i] = in[i];
    }
}

__global__ void copy_tail_kernel(const float* __restrict__ in, float* __restrict__ out,
                                 long long start, long long n) {
    long long i = start + blockIdx.x * blockDim.x + threadIdx.x;
    if (i < n) out[i] = in[i];
}

extern "C" void kernel_launch(void* const* d_in, const int* in_sizes, int n_in,
                              void* d_out, int out_size) {
    const float* x = (const float*)d_in[0];
    float* out = (float*)d_out;
    long long n = (long long)out_size;          // 32*512*4096 = 67108864
    long long n4 = n >> 2;                      // divisible by 4 here

    const int threads = 512;
    // ~4 waves over 148 SMs at occupancy 2 CTAs/SM: plenty of MLP, even balance.
    int blocks = 148 * 2 * 4;
    long long needed = (n4 + threads - 1) / threads;
    if ((long long)blocks > needed) blocks = (int)needed;
    if (blocks < 1) blocks = 1;

    copy_identity_kernel<<<blocks, threads>>>((const float4*)x, (float4*)out, n4);

    long long tail_start = n4 << 2;
    if (tail_start < n) {
        long long tail = n - tail_start;
        copy_tail_kernel<<<(unsigned)((tail + 255) / 256), 256>>>(x, out, tail_start, n);
    }
}